// round 15
// baseline (speedup 1.0000x reference)
#include <cuda_runtime.h>
#include <cuda_fp16.h>
#include <cstdint>
#include <math.h>

#define F_DIM 2048
#define K_DIM 128
#define BM    128
#define BK    32
#define NT    (F_DIM / BK)     // 64 k-tiles

// ---- smem layout (bytes) ----
#define A_BUF_B   (16 * 528)              // 8448
#define SM_B      (2 * A_BUF_B)           // 16896
#define B_STR_U   136
#define B_BUF_U   (16 * B_STR_U)          // 2176 uint32 = 8704 B
#define SM_PS     (SM_B + 2 * B_BUF_U * 4)    // 34304
#define SM_RLIN   (SM_PS + 2048)
#define SM_RT     (SM_RLIN + 512)
#define SMEM_TOTAL (SM_RT + 512)          // 37376 < 48K -> static

// g_wpk: fp16-pair-packed W, cols PERMUTED within each 32-block so that the
// consumer's 4 j-fragments are contiguous (slot = (n&~31)|((n&7)<<2)|((n>>3)&3))
__device__ uint32_t g_wpk[(F_DIM / 2) * K_DIM];
__device__ float2   g_ws[F_DIM];          // {wlin[f], exact sum_k W[f,k]^2}

__device__ __forceinline__ uint32_t pack2h(float a, float b) {
    __half2 h = __floats2half2_rn(a, b);
    return *reinterpret_cast<uint32_t*>(&h);
}
__device__ __forceinline__ void mma_f16(float* d, uint32_t a0, uint32_t a1,
                                        uint32_t a2, uint32_t a3,
                                        uint32_t b0, uint32_t b1) {
    asm volatile(
        "mma.sync.aligned.m16n8k16.row.col.f32.f16.f16.f32 "
        "{%0,%1,%2,%3}, {%4,%5,%6,%7}, {%8,%9}, {%0,%1,%2,%3};"
        : "+f"(d[0]), "+f"(d[1]), "+f"(d[2]), "+f"(d[3])
        : "r"(a0), "r"(a1), "r"(a2), "r"(a3), "r"(b0), "r"(b1));
}

// ---------------- fused prologue: s_f, wlin, fp16 pair-pack (permuted) ----------------
__global__ void prep_kernel(const float* __restrict__ kern,
                            const float* __restrict__ wlin) {
    const int gw = (blockIdx.x * blockDim.x + threadIdx.x) >> 5;  // 0..511
    const int lane = threadIdx.x & 31;
    float4 prev = make_float4(0.f, 0.f, 0.f, 0.f);
#pragma unroll
    for (int rr = 0; rr < 4; ++rr) {
        const int f = gw * 4 + rr;
        float4 v = *reinterpret_cast<const float4*>(kern + (size_t)f * K_DIM + lane * 4);
        float s = v.x * v.x + v.y * v.y + v.z * v.z + v.w * v.w;
#pragma unroll
        for (int off = 16; off >= 1; off >>= 1)
            s += __shfl_xor_sync(0xffffffffu, s, off);
        if (lane == 0) g_ws[f] = make_float2(wlin[f], s);
        if ((rr & 1) == 0) {
            prev = v;
        } else {
            uint32_t pk[4];
            pk[0] = pack2h(prev.x, v.x);
            pk[1] = pack2h(prev.y, v.y);
            pk[2] = pack2h(prev.z, v.z);
            pk[3] = pack2h(prev.w, v.w);
            uint32_t* row = g_wpk + (size_t)(gw * 2 + (rr >> 1)) * K_DIM;
#pragma unroll
            for (int e = 0; e < 4; ++e) {
                int n = lane * 4 + e;
                int pos = (n & ~31) | ((n & 7) << 2) | ((n >> 3) & 3);
                row[pos] = pk[e];
            }
        }
    }
}

// ---------------- main kernel: 512 threads, fp16, 2-tile LDG runway ----------------
__global__ __launch_bounds__(512, 1) void fm_mma_kernel(
    const float* __restrict__ X, const float* __restrict__ blin,
    float* __restrict__ out) {
    __shared__ __align__(16) char smem[SMEM_TOTAL];
    float* pS     = reinterpret_cast<float*>(smem + SM_PS);
    float* rowLin = reinterpret_cast<float*>(smem + SM_RLIN);
    float* rowT   = reinterpret_cast<float*>(smem + SM_RT);

    const int tid  = threadIdx.x;
    const int lane = tid & 31;
    const int wid  = tid >> 5;
    const int wm   = wid >> 2;              // 0..3 (32-row slice)
    const int wn   = wid & 3;               // 0..3 (32-col slice)
    const int l4   = lane >> 2;
    const int c0   = lane & 3;
    const int blockRow = blockIdx.x * BM;
    const bool isA = (tid < 256);

    // A loader mapping (tid 0..255)
    const int rid  = tid >> 2;
    const int cseg = tid & 3;
    const int rlow = (rid & 7) | ((rid >> 3) << 4);
    const int gA   = rid >> 3;
    const int rloc = rid & 7;
    // B loader mapping (tid 256..511)
    const int t2   = tid & 255;
    const int pB   = t2 >> 4;
    const int n16  = t2 & 15;

    const float* xLo = X + (size_t)(blockRow + rlow) * F_DIM + cseg * 8;
    const float* xHi = xLo + 8 * F_DIM;
    const float4* wsP = reinterpret_cast<const float4*>(g_ws) + cseg * 4;

    float linLo = 0.f, linHi = 0.f, tLo = 0.f, tHi = 0.f;
    float acc[2][4][4];
#pragma unroll
    for (int i = 0; i < 2; ++i)
#pragma unroll
        for (int j = 0; j < 4; ++j)
#pragma unroll
            for (int e = 0; e < 4; ++e) acc[i][j][e] = 0.f;

    float4 st[2][4];   // 2-slot staging

    auto ldg_tile = [&](int t, int slot) {
        float4* s = st[slot];
        if (isA) {
            const int f0 = t * BK;
            s[0] = *reinterpret_cast<const float4*>(xLo + f0);
            s[1] = *reinterpret_cast<const float4*>(xLo + f0 + 4);
            s[2] = *reinterpret_cast<const float4*>(xHi + f0);
            s[3] = *reinterpret_cast<const float4*>(xHi + f0 + 4);
            const float4* wp = wsP + f0 / 2;
            const float* lo = reinterpret_cast<const float*>(&s[0]);
            const float* hi = reinterpret_cast<const float*>(&s[2]);
#pragma unroll
            for (int u = 0; u < 4; ++u) {
                float4 g = __ldg(wp + u);
                float a0 = lo[2 * u], a1 = lo[2 * u + 1];
                float b0 = hi[2 * u], b1 = hi[2 * u + 1];
                linLo += a0 * g.x + a1 * g.z;  tLo += a0 * a0 * g.y + a1 * a1 * g.w;
                linHi += b0 * g.x + b1 * g.z;  tHi += b0 * b0 * g.y + b1 * b1 * g.w;
            }
        } else {
            const uint32_t* src = g_wpk + (size_t)(t * 16 + pB) * K_DIM + n16 * 8;
            *reinterpret_cast<uint4*>(&s[0]) = *reinterpret_cast<const uint4*>(src);
            *reinterpret_cast<uint4*>(&s[1]) = *reinterpret_cast<const uint4*>(src + 4);
        }
    };
    auto sts_tile = [&](int buf, int slot) {
        const float4* s = st[slot];
        if (isA) {
            char* ad = smem + buf * A_BUF_B + (gA * 2 + (cseg >> 1)) * 528;
            const float* lo = reinterpret_cast<const float*>(&s[0]);
            const float* hi = reinterpret_cast<const float*>(&s[2]);
            const int hs = cseg & 1;
#pragma unroll
            for (int c = 0; c < 4; ++c) {
                uint2 v;
                v.x = pack2h(lo[2 * c], lo[2 * c + 1]);
                v.y = pack2h(hi[2 * c], hi[2 * c + 1]);
                *reinterpret_cast<uint2*>(ad + (4 * rloc + c) * 16 + hs * 8) = v;
            }
        } else {
            uint32_t* bd = reinterpret_cast<uint32_t*>(smem + SM_B) +
                           buf * B_BUF_U + pB * B_STR_U + n16 * 8;
            *reinterpret_cast<uint4*>(bd) = *reinterpret_cast<const uint4*>(&s[0]);
            *reinterpret_cast<uint4*>(bd + 4) = *reinterpret_cast<const uint4*>(&s[1]);
        }
    };

    // prologue: 2-tile runway
    ldg_tile(0, 0);
    ldg_tile(1, 1);
    sts_tile(0, 0);
    __syncthreads();

    for (int t = 0; t < NT; ++t) {
        if (t + 2 < NT) ldg_tile(t + 2, t & 1);

        // ---- compute tile t from buffer t&1 ----
        {
            const char* ab = smem + (t & 1) * A_BUF_B;
            const uint32_t* bs = reinterpret_cast<const uint32_t*>(smem + SM_B) +
                                 (t & 1) * B_BUF_U + c0 * B_STR_U + wn * 32 + l4 * 4;
#pragma unroll
            for (int ks = 0; ks < 2; ++ks) {
                uint4 a0 = *reinterpret_cast<const uint4*>(
                    ab + ((wm * 2 + 0) * 2 + ks) * 528 + lane * 16);
                uint4 a1 = *reinterpret_cast<const uint4*>(
                    ab + ((wm * 2 + 1) * 2 + ks) * 528 + lane * 16);
                const uint32_t* bk = bs + ks * 8 * B_STR_U;
                uint4 B0 = *reinterpret_cast<const uint4*>(bk);
                uint4 B1 = *reinterpret_cast<const uint4*>(bk + 4 * B_STR_U);
                const uint32_t* b0p = reinterpret_cast<const uint32_t*>(&B0);
                const uint32_t* b1p = reinterpret_cast<const uint32_t*>(&B1);
#pragma unroll
                for (int j = 0; j < 4; ++j) {
                    mma_f16(acc[0][j], a0.x, a0.y, a0.z, a0.w, b0p[j], b1p[j]);
                    mma_f16(acc[1][j], a1.x, a1.y, a1.z, a1.w, b0p[j], b1p[j]);
                }
            }
        }

        if (t + 1 < NT) sts_tile((t + 1) & 1, (t + 1) & 1);
        __syncthreads();
    }

    // ---- per-row lin/t reduce (A loaders only) ----
    if (isA) {
        linLo += __shfl_xor_sync(0xffffffffu, linLo, 1);
        linLo += __shfl_xor_sync(0xffffffffu, linLo, 2);
        linHi += __shfl_xor_sync(0xffffffffu, linHi, 1);
        linHi += __shfl_xor_sync(0xffffffffu, linHi, 2);
        tLo += __shfl_xor_sync(0xffffffffu, tLo, 1);
        tLo += __shfl_xor_sync(0xffffffffu, tLo, 2);
        tHi += __shfl_xor_sync(0xffffffffu, tHi, 1);
        tHi += __shfl_xor_sync(0xffffffffu, tHi, 2);
        if (cseg == 0) {
            rowLin[rlow] = linLo;  rowT[rlow] = tLo;
            rowLin[rlow + 8] = linHi;  rowT[rlow + 8] = tHi;
        }
    }

    // ---- epilogue: per-warp sum of squares over its 32 cols ----
#pragma unroll
    for (int i = 0; i < 2; ++i) {
        float sLo = 0.f, sHi = 0.f;
#pragma unroll
        for (int j = 0; j < 4; ++j) {
            sLo += acc[i][j][0] * acc[i][j][0] + acc[i][j][1] * acc[i][j][1];
            sHi += acc[i][j][2] * acc[i][j][2] + acc[i][j][3] * acc[i][j][3];
        }
        sLo += __shfl_xor_sync(0xffffffffu, sLo, 1);
        sLo += __shfl_xor_sync(0xffffffffu, sLo, 2);
        sHi += __shfl_xor_sync(0xffffffffu, sHi, 1);
        sHi += __shfl_xor_sync(0xffffffffu, sHi, 2);
        if (c0 == 0) {
            int rowL = wm * 32 + i * 16 + l4;
            pS[rowL * 4 + wn] = sLo;
            pS[(rowL + 8) * 4 + wn] = sHi;
        }
    }
    __syncthreads();

    if (tid < BM) {
        float ssum = pS[tid * 4] + pS[tid * 4 + 1] + pS[tid * 4 + 2] + pS[tid * 4 + 3];
        float cross = 0.5f * (ssum - rowT[tid]) * (1.0f / (float)K_DIM);
        float z = rowLin[tid] + blin[0] + cross;
        out[blockRow + tid] = 1.0f / (1.0f + expf(-z));
    }
}

extern "C" void kernel_launch(void* const* d_in, const int* in_sizes, int n_in,
                              void* d_out, int out_size) {
    const float* x    = (const float*)d_in[0];
    const float* kern = (const float*)d_in[1];
    const float* wlin = (const float*)d_in[2];
    const float* blin = (const float*)d_in[3];
    float* out = (float*)d_out;
    const int B = out_size;

    prep_kernel<<<64, 256>>>(kern, wlin);
    fm_mma_kernel<<<B / BM, 512>>>(x, blin, out);
}

// round 16
// speedup vs baseline: 1.2611x; 1.2611x over previous
#include <cuda_runtime.h>
#include <cuda_fp16.h>
#include <cstdint>
#include <math.h>

#define F_DIM 2048
#define K_DIM 128
#define BM    128
#define BK    32
#define NT    (F_DIM / BK)     // 64 k-tiles

// ---- smem layout (bytes) ----
#define A_BUF_B   (16 * 528)              // 8448
#define SM_B      (2 * A_BUF_B)           // 16896
#define B_STR_U   136
#define B_BUF_U   (16 * B_STR_U)          // 8704 B
#define SM_PS     (SM_B + 2 * B_BUF_U * 4)    // 34304
#define SM_RLIN   (SM_PS + 2048)
#define SM_RT     (SM_RLIN + 512)
#define SMEM_TOTAL (SM_RT + 512)          // 37376 < 48K -> static

// g_wpk: fp16-pair-packed W, cols PERMUTED within each 32-block:
// slot = (n&~31)|((n&7)<<2)|((n>>3)&3)  =>  consumer j-frags contiguous
__device__ uint32_t g_wpk[(F_DIM / 2) * K_DIM];
__device__ float2   g_ws[F_DIM];          // {wlin[f], exact sum_k W[f,k]^2}

__device__ __forceinline__ uint32_t pack2h(float a, float b) {
    __half2 h = __floats2half2_rn(a, b);
    return *reinterpret_cast<uint32_t*>(&h);
}
__device__ __forceinline__ void mma_f16(float* d, uint32_t a0, uint32_t a1,
                                        uint32_t a2, uint32_t a3,
                                        uint32_t b0, uint32_t b1) {
    asm volatile(
        "mma.sync.aligned.m16n8k16.row.col.f32.f16.f16.f32 "
        "{%0,%1,%2,%3}, {%4,%5,%6,%7}, {%8,%9}, {%0,%1,%2,%3};"
        : "+f"(d[0]), "+f"(d[1]), "+f"(d[2]), "+f"(d[3])
        : "r"(a0), "r"(a1), "r"(a2), "r"(a3), "r"(b0), "r"(b1));
}

// ---------------- fused prologue: s_f, wlin, fp16 pair-pack (permuted) ----------------
__global__ void prep_kernel(const float* __restrict__ kern,
                            const float* __restrict__ wlin) {
    const int gw = (blockIdx.x * blockDim.x + threadIdx.x) >> 5;  // 0..511
    const int lane = threadIdx.x & 31;
    float4 prev = make_float4(0.f, 0.f, 0.f, 0.f);
#pragma unroll
    for (int rr = 0; rr < 4; ++rr) {
        const int f = gw * 4 + rr;
        float4 v = *reinterpret_cast<const float4*>(kern + (size_t)f * K_DIM + lane * 4);
        float s = v.x * v.x + v.y * v.y + v.z * v.z + v.w * v.w;
#pragma unroll
        for (int off = 16; off >= 1; off >>= 1)
            s += __shfl_xor_sync(0xffffffffu, s, off);
        if (lane == 0) g_ws[f] = make_float2(wlin[f], s);
        if ((rr & 1) == 0) {
            prev = v;
        } else {
            uint32_t pk[4];
            pk[0] = pack2h(prev.x, v.x);
            pk[1] = pack2h(prev.y, v.y);
            pk[2] = pack2h(prev.z, v.z);
            pk[3] = pack2h(prev.w, v.w);
            uint32_t* row = g_wpk + (size_t)(gw * 2 + (rr >> 1)) * K_DIM;
#pragma unroll
            for (int e = 0; e < 4; ++e) {
                int n = lane * 4 + e;
                int pos = (n & ~31) | ((n & 7) << 2) | ((n >> 3) & 3);
                row[pos] = pk[e];
            }
        }
    }
}

// ---------------- main kernel: 512 threads, fp16, single-slot staging ----------------
__global__ __launch_bounds__(512, 1) void fm_mma_kernel(
    const float* __restrict__ X, const float* __restrict__ blin,
    float* __restrict__ out) {
    __shared__ __align__(16) char smem[SMEM_TOTAL];
    float* pS     = reinterpret_cast<float*>(smem + SM_PS);
    float* rowLin = reinterpret_cast<float*>(smem + SM_RLIN);
    float* rowT   = reinterpret_cast<float*>(smem + SM_RT);

    const int tid  = threadIdx.x;
    const int lane = tid & 31;
    const int wid  = tid >> 5;
    const int wm   = wid >> 2;              // 0..3 (32-row slice)
    const int wn   = wid & 3;               // 0..3 (32-col slice)
    const int l4   = lane >> 2;
    const int c0   = lane & 3;
    const int blockRow = blockIdx.x * BM;
    const bool isA = (tid < 256);

    // A loader mapping (tid 0..255)
    const int rid  = tid >> 2;
    const int cseg = tid & 3;
    const int rlow = (rid & 7) | ((rid >> 3) << 4);
    const int gA   = rid >> 3;
    const int rloc = rid & 7;
    // B loader mapping (tid 256..511)
    const int t2   = tid & 255;
    const int pB   = t2 >> 4;
    const int n16  = t2 & 15;

    const float* xLo = X + (size_t)(blockRow + rlow) * F_DIM + cseg * 8;
    const float* xHi = xLo + 8 * F_DIM;
    const float4* wsP = reinterpret_cast<const float4*>(g_ws) + cseg * 4;

    float linLo = 0.f, linHi = 0.f, tLo = 0.f, tHi = 0.f;
    float acc[2][4][4];
#pragma unroll
    for (int i = 0; i < 2; ++i)
#pragma unroll
        for (int j = 0; j < 4; ++j)
#pragma unroll
            for (int e = 0; e < 4; ++e) acc[i][j][e] = 0.f;

    float4 st[4];   // single-slot staging (statically indexed)

    auto ldg_tile = [&](int t) {
        if (isA) {
            const int f0 = t * BK;
            st[0] = *reinterpret_cast<const float4*>(xLo + f0);
            st[1] = *reinterpret_cast<const float4*>(xLo + f0 + 4);
            st[2] = *reinterpret_cast<const float4*>(xHi + f0);
            st[3] = *reinterpret_cast<const float4*>(xHi + f0 + 4);
            const float4* wp = wsP + f0 / 2;
            const float* lo = reinterpret_cast<const float*>(&st[0]);
            const float* hi = reinterpret_cast<const float*>(&st[2]);
#pragma unroll
            for (int u = 0; u < 4; ++u) {
                float4 g = __ldg(wp + u);
                float a0 = lo[2 * u], a1 = lo[2 * u + 1];
                float b0 = hi[2 * u], b1 = hi[2 * u + 1];
                linLo += a0 * g.x + a1 * g.z;  tLo += a0 * a0 * g.y + a1 * a1 * g.w;
                linHi += b0 * g.x + b1 * g.z;  tHi += b0 * b0 * g.y + b1 * b1 * g.w;
            }
        } else {
            const uint32_t* src = g_wpk + (size_t)(t * 16 + pB) * K_DIM + n16 * 8;
            *reinterpret_cast<uint4*>(&st[0]) = *reinterpret_cast<const uint4*>(src);
            *reinterpret_cast<uint4*>(&st[1]) = *reinterpret_cast<const uint4*>(src + 4);
        }
    };
    auto sts_tile = [&](int buf) {
        if (isA) {
            char* ad = smem + buf * A_BUF_B + (gA * 2 + (cseg >> 1)) * 528;
            const float* lo = reinterpret_cast<const float*>(&st[0]);
            const float* hi = reinterpret_cast<const float*>(&st[2]);
            const int hs = cseg & 1;
#pragma unroll
            for (int c = 0; c < 4; ++c) {
                uint2 v;
                v.x = pack2h(lo[2 * c], lo[2 * c + 1]);
                v.y = pack2h(hi[2 * c], hi[2 * c + 1]);
                *reinterpret_cast<uint2*>(ad + (4 * rloc + c) * 16 + hs * 8) = v;
            }
        } else {
            uint32_t* bd = reinterpret_cast<uint32_t*>(smem + SM_B) +
                           buf * B_BUF_U + pB * B_STR_U + n16 * 8;
            *reinterpret_cast<uint4*>(bd) = *reinterpret_cast<const uint4*>(&st[0]);
            *reinterpret_cast<uint4*>(bd + 4) = *reinterpret_cast<const uint4*>(&st[1]);
        }
    };

    ldg_tile(0);
    sts_tile(0);
    __syncthreads();

    for (int t = 0; t < NT; ++t) {
        const int nt = t + 1;
        if (nt < NT) ldg_tile(nt);

        // ---- compute tile t from buffer t&1 (B frags via LDS.128) ----
        {
            const char* ab = smem + (t & 1) * A_BUF_B;
            const uint32_t* bs = reinterpret_cast<const uint32_t*>(smem + SM_B) +
                                 (t & 1) * B_BUF_U + c0 * B_STR_U + wn * 32 + l4 * 4;
#pragma unroll
            for (int ks = 0; ks < 2; ++ks) {
                uint4 a0 = *reinterpret_cast<const uint4*>(
                    ab + ((wm * 2 + 0) * 2 + ks) * 528 + lane * 16);
                uint4 a1 = *reinterpret_cast<const uint4*>(
                    ab + ((wm * 2 + 1) * 2 + ks) * 528 + lane * 16);
                const uint32_t* bk = bs + ks * 8 * B_STR_U;
                uint4 B0 = *reinterpret_cast<const uint4*>(bk);
                uint4 B1 = *reinterpret_cast<const uint4*>(bk + 4 * B_STR_U);
                const uint32_t* b0p = reinterpret_cast<const uint32_t*>(&B0);
                const uint32_t* b1p = reinterpret_cast<const uint32_t*>(&B1);
#pragma unroll
                for (int j = 0; j < 4; ++j) {
                    mma_f16(acc[0][j], a0.x, a0.y, a0.z, a0.w, b0p[j], b1p[j]);
                    mma_f16(acc[1][j], a1.x, a1.y, a1.z, a1.w, b0p[j], b1p[j]);
                }
            }
        }

        if (nt < NT) sts_tile(nt & 1);
        __syncthreads();
    }

    // ---- per-row lin/t reduce (A loaders only) ----
    if (isA) {
        linLo += __shfl_xor_sync(0xffffffffu, linLo, 1);
        linLo += __shfl_xor_sync(0xffffffffu, linLo, 2);
        linHi += __shfl_xor_sync(0xffffffffu, linHi, 1);
        linHi += __shfl_xor_sync(0xffffffffu, linHi, 2);
        tLo += __shfl_xor_sync(0xffffffffu, tLo, 1);
        tLo += __shfl_xor_sync(0xffffffffu, tLo, 2);
        tHi += __shfl_xor_sync(0xffffffffu, tHi, 1);
        tHi += __shfl_xor_sync(0xffffffffu, tHi, 2);
        if (cseg == 0) {
            rowLin[rlow] = linLo;  rowT[rlow] = tLo;
            rowLin[rlow + 8] = linHi;  rowT[rlow + 8] = tHi;
        }
    }

    // ---- epilogue: per-warp sum of squares over its 32 cols ----
#pragma unroll
    for (int i = 0; i < 2; ++i) {
        float sLo = 0.f, sHi = 0.f;
#pragma unroll
        for (int j = 0; j < 4; ++j) {
            sLo += acc[i][j][0] * acc[i][j][0] + acc[i][j][1] * acc[i][j][1];
            sHi += acc[i][j][2] * acc[i][j][2] + acc[i][j][3] * acc[i][j][3];
        }
        sLo += __shfl_xor_sync(0xffffffffu, sLo, 1);
        sLo += __shfl_xor_sync(0xffffffffu, sLo, 2);
        sHi += __shfl_xor_sync(0xffffffffu, sHi, 1);
        sHi += __shfl_xor_sync(0xffffffffu, sHi, 2);
        if (c0 == 0) {
            int rowL = wm * 32 + i * 16 + l4;
            pS[rowL * 4 + wn] = sLo;
            pS[(rowL + 8) * 4 + wn] = sHi;
        }
    }
    __syncthreads();

    if (tid < BM) {
        float ssum = pS[tid * 4] + pS[tid * 4 + 1] + pS[tid * 4 + 2] + pS[tid * 4 + 3];
        float cross = 0.5f * (ssum - rowT[tid]) * (1.0f / (float)K_DIM);
        float z = rowLin[tid] + blin[0] + cross;
        out[blockRow + tid] = 1.0f / (1.0f + expf(-z));
    }
}

extern "C" void kernel_launch(void* const* d_in, const int* in_sizes, int n_in,
                              void* d_out, int out_size) {
    const float* x    = (const float*)d_in[0];
    const float* kern = (const float*)d_in[1];
    const float* wlin = (const float*)d_in[2];
    const float* blin = (const float*)d_in[3];
    float* out = (float*)d_out;
    const int B = out_size;

    prep_kernel<<<64, 256>>>(kern, wlin);
    fm_mma_kernel<<<B / BM, 512>>>(x, blin, out);
}